// round 16
// baseline (speedup 1.0000x reference)
#include <cuda_runtime.h>
#include <cuda_bf16.h>
#include <math.h>
#include <stdint.h>

#define T_  512
#define B_  16
#define D_  512
#define H_  8
#define DH_ 64
#define DI_ 2048
#define L_  4
#define SCALE_ (0.125f)
#define NEG_INF_ (-1e9f)
#define RKROWS 2112                       // 2048 + 64 slack rows per layer

typedef __nv_bfloat16 bf16;

// ------------------------- static device scratch -------------------------
__device__ float g_h   [(size_t)T_*B_*D_];
__device__ bf16  g_hh  [(size_t)T_*B_*D_];
__device__ bf16  g_hl  [(size_t)T_*B_*D_];
__device__ bf16  g_posh[(size_t)2048*D_];
__device__ bf16  g_posl[(size_t)2048*D_];
// per-head attention operands, z = b*8 + n
__device__ bf16  g_qw_h[(size_t)128*512*64], g_qw_l[(size_t)128*512*64]; // pre-scaled
__device__ bf16  g_qr_h[(size_t)128*512*64], g_qr_l[(size_t)128*512*64];
__device__ bf16  g_k_h [(size_t)128*512*64], g_k_l [(size_t)128*512*64];
__device__ bf16  g_vth [(size_t)128*64*512], g_vtl [(size_t)128*64*512]; // [(z)*64+d][t]
__device__ bf16  g_rkbf_h[(size_t)L_*RKROWS*512], g_rkbf_l[(size_t)L_*RKROWS*512];
__device__ bf16  g_vech[(size_t)T_*B_*D_];
__device__ bf16  g_vecl[(size_t)T_*B_*D_];
__device__ float g_t1  [(size_t)T_*B_*D_];
__device__ bf16  g_ffh [(size_t)T_*B_*DI_];
__device__ bf16  g_ffl [(size_t)T_*B_*DI_];
__device__ unsigned char g_pad[B_*T_];
__device__ int   g_len[B_];
// transposed + split weights: [L][N][K]
__device__ bf16 g_qkvT_h[(size_t)L_*1536*512], g_qkvT_l[(size_t)L_*1536*512];
__device__ bf16 g_rkT_h [(size_t)L_*512*512],  g_rkT_l [(size_t)L_*512*512];
__device__ bf16 g_oT_h  [(size_t)L_*512*512],  g_oT_l  [(size_t)L_*512*512];
__device__ bf16 g_w1T_h [(size_t)L_*2048*512], g_w1T_l [(size_t)L_*2048*512];
__device__ bf16 g_w2T_h [(size_t)L_*512*2048], g_w2T_l [(size_t)L_*512*2048];

// ------------------------- helpers -------------------------
__device__ __forceinline__ void fsplit(float v, unsigned short& hi, unsigned short& lo)
{
    bf16 h = __float2bfloat16(v);
    float rem = v - __bfloat162float(h);
    bf16 l = __float2bfloat16(rem);
    hi = __bfloat16_as_ushort(h);
    lo = __bfloat16_as_ushort(l);
}

__device__ __forceinline__ void split2_store(bf16* oh, bf16* ol, size_t idx, float v0, float v1)
{
    unsigned short h0,l0,h1,l1;
    fsplit(v0,h0,l0); fsplit(v1,h1,l1);
    *(unsigned*)(oh + idx) = (unsigned)h0 | ((unsigned)h1 << 16);
    *(unsigned*)(ol + idx) = (unsigned)l0 | ((unsigned)l1 << 16);
}

__device__ __forceinline__ void mma16816(float* d, const unsigned* a, const unsigned* b)
{
    asm volatile(
        "mma.sync.aligned.m16n8k16.row.col.f32.bf16.bf16.f32 "
        "{%0,%1,%2,%3},{%4,%5,%6,%7},{%8,%9},{%0,%1,%2,%3};"
        : "+f"(d[0]), "+f"(d[1]), "+f"(d[2]), "+f"(d[3])
        : "r"(a[0]), "r"(a[1]), "r"(a[2]), "r"(a[3]), "r"(b[0]), "r"(b[1]));
}

__device__ __forceinline__ void ldsm4(unsigned* d, uint32_t a)
{
    asm volatile("ldmatrix.sync.aligned.m8n8.x4.shared.b16 {%0,%1,%2,%3}, [%4];"
        : "=r"(d[0]), "=r"(d[1]), "=r"(d[2]), "=r"(d[3]) : "r"(a));
}

__device__ __forceinline__ void ldsm2(unsigned* d, uint32_t a)
{
    asm volatile("ldmatrix.sync.aligned.m8n8.x2.shared.b16 {%0,%1}, [%2];"
        : "=r"(d[0]), "=r"(d[1]) : "r"(a));
}

__device__ __forceinline__ void cpasync16(uint32_t saddr, const void* gptr)
{
    asm volatile("cp.async.cg.shared.global [%0], [%1], 16;" :: "r"(saddr), "l"(gptr));
}
__device__ __forceinline__ void cpcommit() { asm volatile("cp.async.commit_group;"); }
template<int N> __device__ __forceinline__ void cpwaitN()
{ asm volatile("cp.async.wait_group %0;" :: "n"(N)); }

// ------------------------- weight transpose + split (merged launches) -------------------------
__device__ __forceinline__ void wtrans_tile(const float* Wz, bf16* ohz, bf16* olz,
                                            int K, int N, int n0, int k0)
{
    __shared__ float t[32][33];
    int tx = threadIdx.x & 31, ty = threadIdx.x >> 5;
    #pragma unroll
    for (int i = 0; i < 4; ++i)
        t[ty + 8*i][tx] = Wz[(size_t)(k0 + ty + 8*i) * N + n0 + tx];
    __syncthreads();
    #pragma unroll
    for (int i = 0; i < 4; ++i) {
        int n = n0 + ty + 8*i, k = k0 + tx;
        unsigned short h, l;
        fsplit(t[tx][ty + 8*i], h, l);
        ohz[(size_t)n * K + k] = __ushort_as_bfloat16(h);
        olz[(size_t)n * K + k] = __ushort_as_bfloat16(l);
    }
}

__global__ __launch_bounds__(256)
void wtransA_kernel(const float* __restrict__ qkvw, const float* __restrict__ w1)
{
    int z = blockIdx.z, bx = blockIdx.x, k0 = blockIdx.y * 32;
    if (bx < 48) {
        wtrans_tile(qkvw + (size_t)z*512*1536, g_qkvT_h + (size_t)z*1536*512,
                    g_qkvT_l + (size_t)z*1536*512, 512, 1536, bx*32, k0);
    } else {
        wtrans_tile(w1 + (size_t)z*512*2048, g_w1T_h + (size_t)z*2048*512,
                    g_w1T_l + (size_t)z*2048*512, 512, 2048, (bx-48)*32, k0);
    }
}

__global__ __launch_bounds__(256)
void wtransB_kernel(const float* __restrict__ rnetw, const float* __restrict__ ow,
                    const float* __restrict__ w2)
{
    int z = blockIdx.z, n0 = blockIdx.x * 32, by = blockIdx.y;
    if (by < 16) {
        wtrans_tile(rnetw + (size_t)z*512*512, g_rkT_h + (size_t)z*512*512,
                    g_rkT_l + (size_t)z*512*512, 512, 512, n0, by*32);
    } else if (by < 32) {
        wtrans_tile(ow + (size_t)z*512*512, g_oT_h + (size_t)z*512*512,
                    g_oT_l + (size_t)z*512*512, 512, 512, n0, (by-16)*32);
    } else {
        wtrans_tile(w2 + (size_t)z*2048*512, g_w2T_h + (size_t)z*512*2048,
                    g_w2T_l + (size_t)z*512*2048, 2048, 512, n0, (by-32)*32);
    }
}

// ------------------------- fused mask + positional embeddings + lengths ----------------------
__global__ void posmask_kernel(const unsigned char* __restrict__ raw,
                               unsigned char* __restrict__ pad,
                               bf16* __restrict__ ph, bf16* __restrict__ pl,
                               int* __restrict__ len)
{
    int gid = blockIdx.x * blockDim.x + threadIdx.x;
    unsigned char b0 = raw[0], b1 = raw[1];
    int mode = (b0 == 1 && b1 == 1) ? 0 : ((b0 == 1) ? 1 : 2);
    if (gid < B_ * T_) {
        bool m;
        if (mode == 0)      m = raw[gid] != 0;
        else if (mode == 1) m = ((const int*)raw)[gid] != 0;
        else                m = ((const float*)raw)[gid] != 0.0f;
        pad[gid] = m ? 0 : 1;
    }
    if (blockIdx.x == 0) {
        int w = threadIdx.x >> 5, lane = threadIdx.x & 31;
        for (int bb = w; bb < B_; bb += 8) {
            int s = 0;
            #pragma unroll
            for (int k = 0; k < 16; ++k) {
                int idx = bb * 512 + lane + 32 * k;
                bool m;
                if (mode == 0)      m = raw[idx] != 0;
                else if (mode == 1) m = ((const int*)raw)[idx] != 0;
                else                m = ((const float*)raw)[idx] != 0.0f;
                s += m ? 1 : 0;
            }
            #pragma unroll
            for (int o = 16; o; o >>= 1) s += __shfl_xor_sync(0xffffffffu, s, o);
            if (lane == 0) len[bb] = s;
        }
    }
    int idx = gid - B_ * T_;
    if (idx < 0 || idx >= 2048 * D_) return;
    int m2 = idx / D_;
    int k = idx - m2 * D_;
    int grp = m2 >> 10;
    int mm  = m2 & 1023;
    float p = (grp == 0) ? (float)(T_ - mm) : (float)(mm - T_);
    int kk = (k < 256) ? k : (k - 256);
    float invf = powf(10000.0f, -((float)(2 * kk) / (float)D_));
    float s = p * invf;
    float v = (k < 256) ? sinf(s) : cosf(s);
    unsigned short h, l;
    fsplit(v, h, l);
    ph[idx] = __ushort_as_bfloat16(h);
    pl[idx] = __ushort_as_bfloat16(l);
}

// ------------------------- layernorm v4: warp-per-row, single input, no smem ---------------
__global__ __launch_bounds__(256)
void ln4_kernel(const float* __restrict__ x,
                const float* __restrict__ g, const float* __restrict__ be,
                float* __restrict__ out_seq, bf16* __restrict__ outh, bf16* __restrict__ outl,
                float* __restrict__ outb0, float* __restrict__ outb1, int in_bt)
{
    int w = threadIdx.x >> 5, lane = threadIdx.x & 31;
    int row = blockIdx.x * 8 + w;
    int t = row / B_, b = row - t * B_;
    size_t iseq = (size_t)row * D_;
    size_t ibt  = ((size_t)b * T_ + t) * D_;
    const float* px = x + (in_bt ? ibt : iseq);
    float4 v[4];
    #pragma unroll
    for (int k = 0; k < 4; ++k) v[k] = ((const float4*)px)[lane + 32*k];
    float s = 0.f, q = 0.f;
    #pragma unroll
    for (int k = 0; k < 4; ++k) {
        s += v[k].x + v[k].y + v[k].z + v[k].w;
        q += v[k].x*v[k].x + v[k].y*v[k].y + v[k].z*v[k].z + v[k].w*v[k].w;
    }
    #pragma unroll
    for (int o = 16; o; o >>= 1) {
        s += __shfl_xor_sync(0xffffffffu, s, o);
        q += __shfl_xor_sync(0xffffffffu, q, o);
    }
    float mean = s * (1.0f / 512.0f);
    float var  = q * (1.0f / 512.0f) - mean * mean;
    float rs = rsqrtf(var + 1e-6f);
    #pragma unroll
    for (int k = 0; k < 4; ++k) {
        float4 gg = ((const float4*)g)[lane + 32*k];
        float4 bb = ((const float4*)be)[lane + 32*k];
        float4 y;
        y.x = (v[k].x - mean) * rs * gg.x + bb.x;
        y.y = (v[k].y - mean) * rs * gg.y + bb.y;
        y.z = (v[k].z - mean) * rs * gg.z + bb.z;
        y.w = (v[k].w - mean) * rs * gg.w + bb.w;
        ((float4*)(out_seq + iseq))[lane + 32*k] = y;
        unsigned short h0,l0,h1,l1,h2,l2,h3,l3;
        fsplit(y.x, h0, l0); fsplit(y.y, h1, l1);
        fsplit(y.z, h2, l2); fsplit(y.w, h3, l3);
        uint2 ph = { (unsigned)h0 | ((unsigned)h1<<16), (unsigned)h2 | ((unsigned)h3<<16) };
        uint2 pl = { (unsigned)l0 | ((unsigned)l1<<16), (unsigned)l2 | ((unsigned)l3<<16) };
        ((uint2*)(outh + iseq))[lane + 32*k] = ph;
        ((uint2*)(outl + iseq))[lane + 32*k] = pl;
        if (outb0) ((float4*)(outb0 + ibt))[lane + 32*k] = y;
        if (outb1) ((float4*)(outb1 + ibt))[lane + 32*k] = y;
    }
}

// ------------------------- GEMM v3 (dense layers), LDSM fragments -------------------------
// MODE 0: Cf fp32 (+bias);  MODE 1: bias+relu+split;  MODE 2: QKV epilogue;
// MODE 4: split row-major;  MODE 5: Cf fp32 + bias + residual (bias2 = residual base)
// blockIdx.z selects an independent problem: B += z*zStrB, O/Cf += z*zStrO.
template<int BM, int BN, int WM, int WN, int MODE>
__global__ void __launch_bounds__(256)
gemm_v3(const bf16* __restrict__ Ah, const bf16* __restrict__ Al,
        const bf16* __restrict__ Bh, const bf16* __restrict__ Bl,
        const float* __restrict__ bias, const float* __restrict__ bias2,
        float* __restrict__ Cf, bf16* __restrict__ Oh, bf16* __restrict__ Ol,
        int M, int N, int K, size_t zStrB, size_t zStrO)
{
    constexpr int MT = WM / 16, NT = WN / 8;
    constexpr int NWM = BM / WM;
    constexpr int NA = BM * 4, NB = BN * 4, TOTAL = 2 * (NA + NB);
    constexpr int SA = BM * 20, SB = BN * 20;
    constexpr int S = 2 * SA + 2 * SB;

    extern __shared__ uint32_t smem[];
    uint32_t sbase = (uint32_t)__cvta_generic_to_shared(smem);

    size_t zb_off = (size_t)blockIdx.z * zStrB;
    size_t zo_off = (size_t)blockIdx.z * zStrO;
    Bh += zb_off; Bl += zb_off;
    if (Oh) { Oh += zo_off; Ol += zo_off; }
    if (Cf) Cf += zo_off;

    int m0 = blockIdx.y * BM, n0 = blockIdx.x * BN;
    int tid = threadIdx.x, lane = tid & 31, w = tid >> 5;
    int wm = (w % NWM) * WM, wn = (w / NWM) * WN;
    int r = lane >> 2, c = lane & 3;

    float acc[MT][NT][4];
    #pragma unroll
    for (int i = 0; i < MT; ++i)
        #pragma unroll
        for (int j = 0; j < NT; ++j)
            #pragma unroll
            for (int q = 0; q < 4; ++q) acc[i][j][q] = 0.f;

    auto prefetch = [&](int kt, int st) {
        uint32_t base = sbase + (uint32_t)st * S * 4;
        #pragma unroll
        for (int l = 0; l < TOTAL / 256; ++l) {
            int q = tid + l * 256;
            const bf16* gp; uint32_t off;
            if (q < NA) {
                int row = q >> 2, seg = q & 3;
                gp = Ah + (size_t)(m0 + row) * K + kt + seg * 8;
                off = row * 20 + seg * 4;
            } else if (q < 2 * NA) {
                int p = q - NA; int row = p >> 2, seg = p & 3;
                gp = Al + (size_t)(m0 + row) * K + kt + seg * 8;
                off = SA + row * 20 + seg * 4;
            } else if (q < 2 * NA + NB) {
                int p = q - 2 * NA; int row = p >> 2, seg = p & 3;
                gp = Bh + (size_t)(n0 + row) * K + kt + seg * 8;
                off = 2 * SA + row * 20 + seg * 4;
            } else {
                int p = q - 2 * NA - NB; int row = p >> 2, seg = p & 3;
                gp = Bl + (size_t)(n0 + row) * K + kt + seg * 8;
                off = 2 * SA + SB + row * 20 + seg * 4;
            }
            cpasync16(base + off * 4, gp);
        }
        cpcommit();
    };

    uint32_t aRowOff = (lane & 7) + ((lane >> 3) & 1) * 8;
    uint32_t aChunk  = (lane >> 4) * 16;
    uint32_t bRowOff = lane & 7;
    uint32_t bChunk  = ((lane >> 3) & 1) * 16;

    auto compute = [&](int st) {
        uint32_t stb = sbase + (uint32_t)st * S * 4;
        #pragma unroll
        for (int ks = 0; ks < 2; ++ks) {
            unsigned ah[MT][4], al[MT][4];
            #pragma unroll
            for (int mt = 0; mt < MT; ++mt) {
                uint32_t ab = stb + (uint32_t)(wm + mt * 16 + aRowOff) * 80 + ks * 32 + aChunk;
                ldsm4(ah[mt], ab);
                ldsm4(al[mt], ab + SA * 4);
            }
            #pragma unroll
            for (int nt = 0; nt < NT; ++nt) {
                uint32_t bb = stb + 2u * SA * 4 + (uint32_t)(wn + nt * 8 + bRowOff) * 80
                              + ks * 32 + bChunk;
                unsigned bh[2], bl[2];
                ldsm2(bh, bb);
                ldsm2(bl, bb + SB * 4);
                #pragma unroll
                for (int mt = 0; mt < MT; ++mt) {
                    mma16816(acc[mt][nt], ah[mt], bh);
                    mma16816(acc[mt][nt], ah[mt], bl);
                    mma16816(acc[mt][nt], al[mt], bh);
                }
            }
        }
    };

    int nk = K / 32;
    prefetch(0, 0);
    for (int i = 0; i < nk; ++i) {
        cpwaitN<0>();
        __syncthreads();
        if (i + 1 < nk) prefetch((i + 1) * 32, (i + 1) & 1);
        compute(i & 1);
    }

    #pragma unroll
    for (int mt = 0; mt < MT; ++mt) {
        int row = m0 + wm + mt * 16 + r;
        #pragma unroll
        for (int nt = 0; nt < NT; ++nt) {
            int col = n0 + wn + nt * 8 + 2 * c;
            float v0 = acc[mt][nt][0], v1 = acc[mt][nt][1];
            float v2 = acc[mt][nt][2], v3 = acc[mt][nt][3];
            if (MODE == 0) {
                if (bias) { v0 += bias[col]; v1 += bias[col+1]; v2 += bias[col]; v3 += bias[col+1]; }
                float2 w0 = {v0, v1}, w1 = {v2, v3};
                *(float2*)(Cf + (size_t)row * N + col) = w0;
                *(float2*)(Cf + (size_t)(row + 8) * N + col) = w1;
            } else if (MODE == 5) {
                if (bias) { v0 += bias[col]; v1 += bias[col+1]; v2 += bias[col]; v3 += bias[col+1]; }
                float2 r0 = *(const float2*)(bias2 + (size_t)row * N + col);
                float2 r1 = *(const float2*)(bias2 + (size_t)(row + 8) * N + col);
                v0 += r0.x; v1 += r0.y; v2 += r1.x; v3 += r1.y;
                float2 w0 = {v0, v1}, w1 = {v2, v3};
                *(float2*)(Cf + (size_t)row * N + col) = w0;
                *(float2*)(Cf + (size_t)(row + 8) * N + col) = w1;
            } else if (MODE == 1) {
                float bb0 = bias[col], bb1 = bias[col+1];
                v0 = fmaxf(v0 + bb0, 0.f); v1 = fmaxf(v1 + bb1, 0.f);
                v2 = fmaxf(v2 + bb0, 0.f); v3 = fmaxf(v3 + bb1, 0.f);
                split2_store(Oh, Ol, (size_t)row * N + col, v0, v1);
                split2_store(Oh, Ol, (size_t)(row + 8) * N + col, v2, v3);
            } else if (MODE == 2) {
                if (col < 512) {
                    int hn = col >> 6, d = col & 63;
                    float rw0 = bias[col], rw1 = bias[col+1];
                    float rr0 = bias2[col], rr1 = bias2[col+1];
                    {
                        int bb = row & 15, tt = row >> 4;
                        size_t base = ((size_t)(bb*8+hn)*512 + tt)*64 + d;
                        split2_store(g_qw_h, g_qw_l, base, (v0+rw0)*SCALE_, (v1+rw1)*SCALE_);
                        split2_store(g_qr_h, g_qr_l, base, (v0+rr0)*SCALE_, (v1+rr1)*SCALE_);
                    }
                    {
                        int r2 = row + 8;
                        int bb = r2 & 15, tt = r2 >> 4;
                        size_t base = ((size_t)(bb*8+hn)*512 + tt)*64 + d;
                        split2_store(g_qw_h, g_qw_l, base, (v2+rw0)*SCALE_, (v3+rw1)*SCALE_);
                        split2_store(g_qr_h, g_qr_l, base, (v2+rr0)*SCALE_, (v3+rr1)*SCALE_);
                    }
                } else if (col < 1024) {
                    int cc = col - 512;
                    int hn = cc >> 6, d = cc & 63;
                    {
                        int bb = row & 15, tt = row >> 4;
                        size_t base = ((size_t)(bb*8+hn)*512 + tt)*64 + d;
                        split2_store(g_k_h, g_k_l, base, v0, v1);
                    }
                    {
                        int r2 = row + 8;
                        int bb = r2 & 15, tt = r2 >> 4;
                        size_t base = ((size_t)(bb*8+hn)*512 + tt)*64 + d;
                        split2_store(g_k_h, g_k_l, base, v2, v3);
                    }
                } else {
                    int dp = col - 1024;
                    int hn = dp >> 6, d = dp & 63;
                    {
                        int bb = row & 15, tt = row >> 4;
                        size_t base = ((size_t)(bb*8+hn)*64 + d)*512 + tt;
                        unsigned short h, l;
                        fsplit(v0, h, l); g_vth[base] = __ushort_as_bfloat16(h); g_vtl[base] = __ushort_as_bfloat16(l);
                        fsplit(v1, h, l); g_vth[base + 512] = __ushort_as_bfloat16(h); g_vtl[base + 512] = __ushort_as_bfloat16(l);
                    }
                    {
                        int r2 = row + 8;
                        int bb = r2 & 15, tt = r2 >> 4;
                        size_t base = ((size_t)(bb*8+hn)*64 + d)*512 + tt;
                        unsigned short h, l;
                        fsplit(v2, h, l); g_vth[base] = __ushort_as_bfloat16(h); g_vtl[base] = __ushort_as_bfloat16(l);
                        fsplit(v3, h, l); g_vth[base + 512] = __ushort_as_bfloat16(h); g_vtl[base + 512] = __ushort_as_bfloat16(l);
                    }
                }
            } else { // MODE 4
                split2_store(Oh, Ol, (size_t)row * N + col, v0, v1);
                split2_store(Oh, Ol, (size_t)(row + 8) * N + col, v2, v3);
            }
        }
    }
}

// ------------------------- fused attention (64-row, 3-deep, unrolled + predicated skip) ------
#define ARENA_ROW 532
#define ARENA_U32 (64*ARENA_ROW)
#define STRM_OFF  ARENA_U32
#define TILE_U32  5120
#define VT_TILE_U32 2560
#define QBUF_OFF  (STRM_OFF + 3*TILE_U32)
#define ATTN_SMEM_U32 (QBUF_OFF + TILE_U32)
#define ATTN_SMEM_BYTES (ATTN_SMEM_U32*4)        // 218112
#define P_LO_OFF 272

__device__ __forceinline__ void load_tile64x64(uint32_t sb, const bf16* gh, const bf16* gl,
                                               int r0, int ld)
{
    int tid = threadIdx.x;
    #pragma unroll
    for (int l = 0; l < 4; ++l) {
        int q = tid + l*256;
        int comp = q >> 9, p = q & 511;
        int row = p >> 3, seg = p & 7;
        int kc = seg >> 2, u = (seg & 3) * 4;
        const bf16* g = (comp ? gl : gh) + (size_t)(r0 + row) * ld + seg * 8;
        uint32_t off = (uint32_t)(comp * 2560 + kc * 1280 + row * 20 + u);
        cpasync16(sb + off * 4, g);
    }
}

__device__ __forceinline__ void load_tile64x32(uint32_t sb, const bf16* gh, const bf16* gl,
                                               int c0, int ld)
{
    int tid = threadIdx.x;
    #pragma unroll
    for (int l = 0; l < 2; ++l) {
        int q = tid + l*256;
        int comp = q >> 8, p = q & 255;
        int row = p >> 2, seg = p & 3;
        const bf16* g = (comp ? gl : gh) + (size_t)row * ld + c0 + seg * 8;
        uint32_t off = (uint32_t)(comp * 1280 + row * 20 + seg * 4);
        cpasync16(sb + off * 4, g);
    }
}

__device__ __forceinline__ void mma_qt(float acc[2][2][4], uint32_t sbase,
                                       int qoff, int toff, int wm, int wn, int lane)
{
    uint32_t aRowOff = (lane & 7) + ((lane >> 3) & 1) * 8;
    uint32_t aChunk  = (lane >> 4) * 16;
    uint32_t bRowOff = lane & 7;
    uint32_t bChunk  = ((lane >> 3) & 1) * 16;
    #pragma unroll
    for (int kc = 0; kc < 2; ++kc) {
        uint32_t qb = sbase + (uint32_t)(qoff + kc*1280) * 4;
        uint32_t tb = sbase + (uint32_t)(toff + kc*1280) * 4;
        #pragma unroll
        for (int ks = 0; ks < 2; ++ks) {
            unsigned ah[2][4], al[2][4];
            #pragma unroll
            for (int mt = 0; mt < 2; ++mt) {
                uint32_t ab = qb + (uint32_t)(wm + mt*16 + aRowOff) * 80 + ks*32 + aChunk;
                ldsm4(ah[mt], ab);
                ldsm4(al[mt], ab + 2560*4);
            }
            #pragma unroll
            for (int nt = 0; nt < 2; ++nt) {
                uint32_t bb = tb + (uint32_t)(wn + nt*8 + bRowOff) * 80 + ks*32 + bChunk;
                unsigned bh[2], bl[2];
                ldsm2(bh, bb);
                ldsm2(bl, bb + 2560*4);
                #pragma unroll
                for (int mt = 0; mt < 2; ++mt) {
                    mma16816(acc[mt][nt], ah[mt], bh);
                    mma16816(acc[mt][nt], ah[mt], bl);
                    mma16816(acc[mt][nt], al[mt], bh);
                }
            }
        }
    }
}

__global__ __launch_bounds__(256)
void attn_fused(const bf16* __restrict__ qwh, const bf16* __restrict__ qwl,
                const bf16* __restrict__ qrh, const bf16* __restrict__ qrl,
                const bf16* __restrict__ kh,  const bf16* __restrict__ kl,
                const bf16* __restrict__ rkh, const bf16* __restrict__ rkl,
                const bf16* __restrict__ vth, const bf16* __restrict__ vtl,
                const unsigned char* __restrict__ pad,
                bf16* __restrict__ vech, bf16* __restrict__ vecl)
{
    extern __shared__ uint32_t sm[];
    float* Sf = (float*)sm;
    uint32_t sb = (uint32_t)__cvta_generic_to_shared(sm);

    int i0 = blockIdx.x * 64;
    int z = blockIdx.y;
    int zb = z >> 3, zn = z & 7;
    int grp = (zb >= 8) ? 1 : 0;
    int tid = threadIdx.x, lane = tid & 31, w = tid >> 5;
    int wm = (w & 1) * 32, wn = (w >> 1) * 16;
    int r = lane >> 2, c = lane & 3;

    int len = g_len[zb];
    int ajt = (len + 63) >> 6;                     // active Phase A j-tiles
    int bmt = min(9, ((len + 62) >> 6) + 1);       // active Phase B m-tiles
    int dkt = (len + 31) >> 5;                     // active Phase D k-tiles

    const size_t zoff = (size_t)z * 512 * 64;
    const bf16* pqwh = qwh + zoff; const bf16* pqwl = qwl + zoff;
    const bf16* pqrh = qrh + zoff; const bf16* pqrl = qrl + zoff;
    const bf16* pkh  = kh  + zoff; const bf16* pkl  = kl  + zoff;
    const bf16* pvth = vth + zoff; const bf16* pvtl = vtl + zoff;
    int m_lo = 449 - i0;
    const bf16* prkh = rkh + ((size_t)(grp*1024 + m_lo)) * 512 + zn * 64;
    const bf16* prkl = rkl + ((size_t)(grp*1024 + m_lo)) * 512 + zn * 64;

    // ---- Phase A: S = qw @ k^T (constant-trip, predicated work) ----
    load_tile64x64(sb + QBUF_OFF*4, pqwh, pqwl, i0, 64);
    load_tile64x64(sb + STRM_OFF*4, pkh, pkl, 0, 64);
    cpcommit();
    if (1 < ajt) load_tile64x64(sb + (STRM_OFF + TILE_U32)*4, pkh, pkl, 64, 64);
    cpcommit();
    #pragma unroll
    for (int jt = 0; jt < 8; ++jt) {
        if (jt + 2 < ajt)
            load_tile64x64(sb + (STRM_OFF + ((jt+2)%3)*TILE_U32)*4, pkh, pkl, (jt+2)*64, 64);
        cpcommit();
        cpwaitN<2>();
        __syncthreads();
        if (jt < ajt) {
            float acc[2][2][4] = {};
            mma_qt(acc, sb, QBUF_OFF, STRM_OFF + (jt%3)*TILE_U32, wm, wn, lane);
            #pragma unroll
            for (int mt = 0; mt < 2; ++mt) {
                int il = wm + mt*16 + r;
                #pragma unroll
                for (int nt = 0; nt < 2; ++nt) {
                    int j = jt*64 + wn + nt*8 + 2*c;
                    *(float2*)(Sf + il*ARENA_ROW + j)     = make_float2(acc[mt][nt][0], acc[mt][nt][1]);
                    *(float2*)(Sf + (il+8)*ARENA_ROW + j) = make_float2(acc[mt][nt][2], acc[mt][nt][3]);
                }
            }
        }
        __syncthreads();
    }
    cpwaitN<0>();

    // ---- Phase B: E = qr @ rk_band^T, scatter-add (constant-trip, predicated) ----
    load_tile64x64(sb + QBUF_OFF*4, pqrh, pqrl, i0, 64);
    load_tile64x64(sb + STRM_OFF*4, prkh, prkl, 0, 512);
    cpcommit();
    if (1 < bmt) load_tile64x64(sb + (STRM_OFF + TILE_U32)*4, prkh, prkl, 64, 512);
    cpcommit();
    #pragma unroll
    for (int mt9 = 0; mt9 < 9; ++mt9) {
        if (mt9 + 2 < bmt)
            load_tile64x64(sb + (STRM_OFF + ((mt9+2)%3)*TILE_U32)*4, prkh, prkl, (mt9+2)*64, 512);
        cpcommit();
        cpwaitN<2>();
        __syncthreads();
        if (mt9 < bmt) {
            float acc[2][2][4] = {};
            mma_qt(acc, sb, QBUF_OFF, STRM_OFF + (mt9%3)*TILE_U32, wm, wn, lane);
            #pragma unroll
            for (int mt = 0; mt < 2; ++mt) {
                #pragma unroll
                for (int nt = 0; nt < 2; ++nt) {
                    int mloc = mt9*64 + wn + nt*8 + 2*c;
                    int il = wm + mt*16 + r;
                    int j = mloc + il - 63;
                    if (j >= 0   && j < 512)   Sf[il*ARENA_ROW + j]       += acc[mt][nt][0];
                    if (j+1 >= 0 && j+1 < 512) Sf[il*ARENA_ROW + j + 1]   += acc[mt][nt][1];
                    int il2 = il + 8;
                    int j2 = mloc + il2 - 63;
                    if (j2 >= 0   && j2 < 512)   Sf[il2*ARENA_ROW + j2]     += acc[mt][nt][2];
                    if (j2+1 >= 0 && j2+1 < 512) Sf[il2*ARENA_ROW + j2 + 1] += acc[mt][nt][3];
                }
            }
        }
        __syncthreads();
    }
    cpwaitN<0>();

    // ---- Phase C: mask + softmax + in-place split-P ----
    {
        const unsigned char* pb = pad + zb * T_;
        for (int rr = 0; rr < 8; ++rr) {
            int il = w*8 + rr;
            float* row = Sf + il*ARENA_ROW;
            float vv[16];
            #pragma unroll
            for (int q4 = 0; q4 < 4; ++q4) {
                int jb = (lane + 32*q4) * 4;
                float4 t = *(float4*)(row + jb);
                unsigned pm = *(const unsigned*)(pb + jb);
                vv[q4*4+0] = (pm & 0xffu)        ? NEG_INF_ : t.x;
                vv[q4*4+1] = (pm & 0xff00u)      ? NEG_INF_ : t.y;
                vv[q4*4+2] = (pm & 0xff0000u)    ? NEG_INF_ : t.z;
                vv[q4*4+3] = (pm & 0xff000000u)  ? NEG_INF_ : t.w;
            }
            float mx = vv[0];
            #pragma unroll
            for (int i = 1; i < 16; ++i) mx = fmaxf(mx, vv[i]);
            #pragma unroll
            for (int o = 16; o; o >>= 1) mx = fmaxf(mx, __shfl_xor_sync(0xffffffffu, mx, o));
            float s = 0.f;
            #pragma unroll
            for (int i = 0; i < 16; ++i) { vv[i] = __expf(vv[i] - mx); s += vv[i]; }
            #pragma unroll
            for (int o = 16; o; o >>= 1) s += __shfl_xor_sync(0xffffffffu, s, o);
            float inv = 1.0f / s;
            uint32_t* rh = sm + il*ARENA_ROW;
            uint32_t* rl = rh + P_LO_OFF;
            #pragma unroll
            for (int q4 = 0; q4 < 4; ++q4) {
                int jj = (lane + 32*q4) * 2;
                unsigned short h0,l0,h1,l1,h2,l2,h3,l3;
                fsplit(vv[q4*4+0]*inv, h0, l0);
                fsplit(vv[q4*4+1]*inv, h1, l1);
                fsplit(vv[q4*4+2]*inv, h2, l2);
                fsplit(vv[q4*4+3]*inv, h3, l3);
                uint2 ph = { (unsigned)h0 | ((unsigned)h1<<16), (unsigned)h2 | ((unsigned)h3<<16) };
                uint2 pl = { (unsigned)l0 | ((unsigned)l1<<16), (unsigned)l2 | ((unsigned)l3<<16) };
                *(uint2*)(rh + jj) = ph;
                *(uint2*)(rl + jj) = pl;
            }
        }
    }
    __syncthreads();

    // ---- Phase D: vec = P @ V^T (constant-trip, predicated; P[j>=len]=0 exactly) ----
    uint32_t aRowOff = (lane & 7) + ((lane >> 3) & 1) * 8;
    uint32_t aChunk  = (lane >> 4) * 16;
    uint32_t bRowOff = lane & 7;
    uint32_t bChunk  = ((lane >> 3) & 1) * 16;
    load_tile64x32(sb + STRM_OFF*4, pvth, pvtl, 0, 512);
    cpcommit();
    if (1 < dkt) load_tile64x32(sb + (STRM_OFF + VT_TILE_U32)*4, pvth, pvtl, 32, 512);
    cpcommit();
    float acc[2][2][4] = {};
    #pragma unroll
    for (int kt = 0; kt < 16; ++kt) {
        if (kt + 2 < dkt)
            load_tile64x32(sb + (STRM_OFF + ((kt+2)%3)*VT_TILE_U32)*4, pvth, pvtl, (kt+2)*32, 512);
        cpcommit();
        cpwaitN<2>();
        __syncthreads();
        if (kt < dkt) {
            uint32_t tbb = sb + (uint32_t)(STRM_OFF + (kt%3)*VT_TILE_U32) * 4;
            #pragma unroll
            for (int ks = 0; ks < 2; ++ks) {
                int g16 = kt*2 + ks;
                unsigned ah[2][4], al[2][4];
                #pragma unroll
                for (int mt = 0; mt < 2; ++mt) {
                    uint32_t ab = sb + (uint32_t)(wm + mt*16 + aRowOff) * (ARENA_ROW*4)
                                  + (uint32_t)g16 * 32 + aChunk;
                    ldsm4(ah[mt], ab);
                    ldsm4(al[mt], ab + P_LO_OFF*4);
                }
                #pragma unroll
                for (int nt = 0; nt < 2; ++nt) {
                    uint32_t bb = tbb + (uint32_t)(wn + nt*8 + bRowOff) * 80 + ks*32 + bChunk;
                    unsigned bh[2], bl[2];
                    ldsm2(bh, bb);
                    ldsm2(bl, bb + 1280*4);
                    #pragma unroll
                    for (int mt = 0; mt < 2; ++mt) {
                        mma16816(acc[mt][nt], ah[mt], bh);
                        mma16816(acc[mt][nt], ah[mt], bl);
                        mma16816(acc[mt][nt], al[mt], bh);
                    }
                }
            }
        }
        __syncthreads();
    }
    cpwaitN<0>();
    #pragma unroll
    for (int mt = 0; mt < 2; ++mt) {
        int i = i0 + wm + mt*16 + r;
        #pragma unroll
        for (int nt = 0; nt < 2; ++nt) {
            int d = wn + nt*8 + 2*c;
            size_t o0 = ((size_t)i * B_ + zb) * 512 + zn * 64 + d;
            size_t o1 = ((size_t)(i + 8) * B_ + zb) * 512 + zn * 64 + d;
            split2_store(vech, vecl, o0, acc[mt][nt][0], acc[mt][nt][1]);
            split2_store(vech, vecl, o1, acc[mt][nt][2], acc[mt][nt][3]);
        }
    }
}

// ------------------------- host orchestration -------------------------
template <typename Tp>
static Tp* symaddr(const void* sym)
{
    void* p = nullptr;
    cudaGetSymbolAddress(&p, sym);
    return (Tp*)p;
}

extern "C" void kernel_launch(void* const* d_in, const int* in_sizes, int n_in,
                              void* d_out, int out_size)
{
    const float* h_in  = (const float*)d_in[0];
    const void*  mraw  = d_in[1];
    const float* rwb   = (const float*)d_in[2];
    const float* rrb   = (const float*)d_in[3];
    const float* tlg   = (const float*)d_in[4];
    const float* tlb   = (const float*)d_in[5];
    const float* qkvw  = (const float*)d_in[6];
    const float* rnetw = (const float*)d_in[7];
    const float* ow    = (const float*)d_in[8];
    const float* alg   = (const float*)d_in[9];
    const float* alb   = (const float*)d_in[10];
    const float* w1    = (const float*)d_in[11];
    const float* b1    = (const float*)d_in[12];
    const float* w2    = (const float*)d_in[13];
    const float* b2    = (const float*)d_in[14];
    const float* flg   = (const float*)d_in[15];
    const float* flb   = (const float*)d_in[16];
    float* out = (float*)d_out;

    float* p_h    = symaddr<float>(g_h);
    bf16*  p_hh   = symaddr<bf16>(g_hh);
    bf16*  p_hl   = symaddr<bf16>(g_hl);
    bf16*  p_posh = symaddr<bf16>(g_posh);
    bf16*  p_posl = symaddr<bf16>(g_posl);
    bf16*  p_qw_h = symaddr<bf16>(g_qw_h); bf16* p_qw_l = symaddr<bf16>(g_qw_l);
    bf16*  p_qr_h = symaddr<bf16>(g_qr_h); bf16* p_qr_l = symaddr<bf16>(g_qr_l);
    bf16*  p_k_h  = symaddr<bf16>(g_k_h);  bf16* p_k_l  = symaddr<bf16>(g_k_l);
    bf16*  p_vth  = symaddr<bf16>(g_vth);  bf16* p_vtl  = symaddr<bf16>(g_vtl);
    bf16*  p_rkbf_h = symaddr<bf16>(g_rkbf_h); bf16* p_rkbf_l = symaddr<bf16>(g_rkbf_l);
    bf16*  p_vech = symaddr<bf16>(g_vech);
    bf16*  p_vecl = symaddr<bf16>(g_vecl);
    float* p_t1   = symaddr<float>(g_t1);
    bf16*  p_ffh  = symaddr<bf16>(g_ffh);
    bf16*  p_ffl  = symaddr<bf16>(g_ffl);
    unsigned char* p_pad = symaddr<unsigned char>(g_pad);
    int*   p_len  = symaddr<int>(g_len);

    bf16* p_qkvT_h = symaddr<bf16>(g_qkvT_h); bf16* p_qkvT_l = symaddr<bf16>(g_qkvT_l);
    bf16* p_rkT_h  = symaddr<bf16>(g_rkT_h);  bf16* p_rkT_l  = symaddr<bf16>(g_rkT_l);
    bf16* p_oT_h   = symaddr<bf16>(g_oT_h);   bf16* p_oT_l   = symaddr<bf16>(g_oT_l);
    bf16* p_w1T_h  = symaddr<bf16>(g_w1T_h);  bf16* p_w1T_l  = symaddr<bf16>(g_w1T_l);
    bf16* p_w2T_h  = symaddr<bf16>(g_w2T_h);  bf16* p_w2T_l  = symaddr<bf16>(g_w2T_l);

    auto k_qkv = gemm_v3<128,128,64,32,2>;
    auto k_rk  = gemm_v3<128,128,64,32,4>;
    auto k_res = gemm_v3<128,128,64,32,5>;
    auto k_ff1 = gemm_v3<128,128,64,32,1>;
    const int SMEM_BIG = (2*128*20 + 2*128*20) * 4 * 2;
    cudaFuncSetAttribute(k_qkv, cudaFuncAttributeMaxDynamicSharedMemorySize, SMEM_BIG);
    cudaFuncSetAttribute(k_rk,  cudaFuncAttributeMaxDynamicSharedMemorySize, SMEM_BIG);
    cudaFuncSetAttribute(k_res, cudaFuncAttributeMaxDynamicSharedMemorySize, SMEM_BIG);
    cudaFuncSetAttribute(k_ff1, cudaFuncAttributeMaxDynamicSharedMemorySize, SMEM_BIG);
    cudaFuncSetAttribute(attn_fused, cudaFuncAttributeMaxDynamicSharedMemorySize, ATTN_SMEM_BYTES);

    const size_t BTD = (size_t)B_ * T_ * D_;
    const size_t RKL = (size_t)RKROWS * 512;

    // pre-loop
    wtransA_kernel<<<dim3(112, 16, L_), 256>>>(qkvw, w1);
    wtransB_kernel<<<dim3(16, 96, L_), 256>>>(rnetw, ow, w2);
    posmask_kernel<<<(2048*D_ + B_*T_ + 255)/256, 256>>>(
        (const unsigned char*)mraw, p_pad, p_posh, p_posl, p_len);
    ln4_kernel<<<T_*B_/8, 256>>>(h_in, tlg, tlb, p_h, p_hh, p_hl, out + BTD, nullptr, 1);
    // ALL layers' rk GEMMs in one launch (z = layer)
    k_rk<<<dim3(512/128, 2048/128, L_), 256, SMEM_BIG>>>(
        p_posh, p_posl, p_rkT_h, p_rkT_l,
        nullptr, nullptr, nullptr, p_rkbf_h, p_rkbf_l, 2048, 512, 512,
        (size_t)512*512, RKL);

    for (int i = 0; i < L_; ++i) {
        // QKV -> qw/qr/k/vT (split, per-head layouts)
        k_qkv<<<dim3(1536/128, (T_*B_)/128), 256, SMEM_BIG>>>(
            p_hh, p_hl, p_qkvT_h + (size_t)i*1536*512, p_qkvT_l + (size_t)i*1536*512,
            rwb, rrb, nullptr, nullptr, nullptr, T_*B_, 1536, 512, 0, 0);
        // fused attention (length-aware, unrolled), layer-i rk slice
        attn_fused<<<dim3(T_/64, B_*H_), 256, ATTN_SMEM_BYTES>>>(
            p_qw_h, p_qw_l, p_qr_h, p_qr_l, p_k_h, p_k_l,
            p_rkbf_h + (size_t)i*RKL, p_rkbf_l + (size_t)i*RKL,
            p_vth, p_vtl, p_pad, p_vech, p_vecl);
        // O proj + residual (t1 = h + attn)
        k_res<<<dim3(512/128, (T_*B_)/128), 256, SMEM_BIG>>>(
            p_vech, p_vecl, p_oT_h + (size_t)i*512*512, p_oT_l + (size_t)i*512*512,
            nullptr, p_h, p_t1, nullptr, nullptr, T_*B_, 512, 512, 0, 0);
        // out1 = LN(t1)
        ln4_kernel<<<T_*B_/8, 256>>>(p_t1, alg + i*D_, alb + i*D_, p_h, p_hh, p_hl,
                                     nullptr, nullptr, 0);
        // FF1
        k_ff1<<<dim3(DI_/128, (T_*B_)/128), 256, SMEM_BIG>>>(
            p_hh, p_hl, p_w1T_h + (size_t)i*2048*512, p_w1T_l + (size_t)i*2048*512,
            b1 + (size_t)i*DI_, nullptr, nullptr, p_ffh, p_ffl, T_*B_, DI_, 512, 0, 0);
        // FF2 + bias + residual (t1 = out1 + ff)
        k_res<<<dim3(512/128, (T_*B_)/128), 256, SMEM_BIG>>>(
            p_ffh, p_ffl, p_w2T_h + (size_t)i*512*2048, p_w2T_l + (size_t)i*512*2048,
            b2 + (size_t)i*D_, p_h, p_t1, nullptr, nullptr, T_*B_, 512, DI_, 0, 0);
        // layer out = LN(t1)
        float* hb0 = out + (size_t)(2 + i) * BTD;
        float* hb1 = (i == L_ - 1) ? out : nullptr;
        ln4_kernel<<<T_*B_/8, 256>>>(p_t1, flg + i*D_, flb + i*D_, p_h, p_hh, p_hl,
                                     hb0, hb1, 0);
    }
}

// round 17
// speedup vs baseline: 1.1574x; 1.1574x over previous
#include <cuda_runtime.h>
#include <cuda_bf16.h>
#include <math.h>
#include <stdint.h>

#define T_  512
#define B_  16
#define D_  512
#define H_  8
#define DH_ 64
#define DI_ 2048
#define L_  4
#define SCALE_ (0.125f)
#define NEG_INF_ (-1e9f)
#define RKROWS 2112                       // 2048 + 64 slack rows per layer

typedef __nv_bfloat16 bf16;

// ------------------------- static device scratch -------------------------
__device__ float g_h   [(size_t)T_*B_*D_];
__device__ bf16  g_hh  [(size_t)T_*B_*D_];
__device__ bf16  g_hl  [(size_t)T_*B_*D_];
__device__ bf16  g_posh[(size_t)2048*D_];
__device__ bf16  g_posl[(size_t)2048*D_];
// per-head attention operands, z = b*8 + n
__device__ bf16  g_qw_h[(size_t)128*512*64], g_qw_l[(size_t)128*512*64]; // pre-scaled
__device__ bf16  g_qr_h[(size_t)128*512*64], g_qr_l[(size_t)128*512*64];
__device__ bf16  g_k_h [(size_t)128*512*64], g_k_l [(size_t)128*512*64];
__device__ bf16  g_vth [(size_t)128*512*64], g_vtl [(size_t)128*512*64]; // V row-major [(z)*512+t][d]
__device__ bf16  g_rkbf_h[(size_t)L_*RKROWS*512], g_rkbf_l[(size_t)L_*RKROWS*512];
__device__ bf16  g_vech[(size_t)T_*B_*D_];
__device__ bf16  g_vecl[(size_t)T_*B_*D_];
__device__ float g_t1  [(size_t)T_*B_*D_];
__device__ bf16  g_ffh [(size_t)T_*B_*DI_];
__device__ bf16  g_ffl [(size_t)T_*B_*DI_];
__device__ unsigned char g_pad[B_*T_];
__device__ int   g_len[B_];
// transposed + split weights: [L][N][K]
__device__ bf16 g_qkvT_h[(size_t)L_*1536*512], g_qkvT_l[(size_t)L_*1536*512];
__device__ bf16 g_rkT_h [(size_t)L_*512*512],  g_rkT_l [(size_t)L_*512*512];
__device__ bf16 g_oT_h  [(size_t)L_*512*512],  g_oT_l  [(size_t)L_*512*512];
__device__ bf16 g_w1T_h [(size_t)L_*2048*512], g_w1T_l [(size_t)L_*2048*512];
__device__ bf16 g_w2T_h [(size_t)L_*512*2048], g_w2T_l [(size_t)L_*512*2048];

// ------------------------- helpers -------------------------
__device__ __forceinline__ void fsplit(float v, unsigned short& hi, unsigned short& lo)
{
    bf16 h = __float2bfloat16(v);
    float rem = v - __bfloat162float(h);
    bf16 l = __float2bfloat16(rem);
    hi = __bfloat16_as_ushort(h);
    lo = __bfloat16_as_ushort(l);
}

__device__ __forceinline__ void split2_store(bf16* oh, bf16* ol, size_t idx, float v0, float v1)
{
    unsigned short h0,l0,h1,l1;
    fsplit(v0,h0,l0); fsplit(v1,h1,l1);
    *(unsigned*)(oh + idx) = (unsigned)h0 | ((unsigned)h1 << 16);
    *(unsigned*)(ol + idx) = (unsigned)l0 | ((unsigned)l1 << 16);
}

__device__ __forceinline__ void mma16816(float* d, const unsigned* a, const unsigned* b)
{
    asm volatile(
        "mma.sync.aligned.m16n8k16.row.col.f32.bf16.bf16.f32 "
        "{%0,%1,%2,%3},{%4,%5,%6,%7},{%8,%9},{%0,%1,%2,%3};"
        : "+f"(d[0]), "+f"(d[1]), "+f"(d[2]), "+f"(d[3])
        : "r"(a[0]), "r"(a[1]), "r"(a[2]), "r"(a[3]), "r"(b[0]), "r"(b[1]));
}

__device__ __forceinline__ void ldsm4(unsigned* d, uint32_t a)
{
    asm volatile("ldmatrix.sync.aligned.m8n8.x4.shared.b16 {%0,%1,%2,%3}, [%4];"
        : "=r"(d[0]), "=r"(d[1]), "=r"(d[2]), "=r"(d[3]) : "r"(a));
}

__device__ __forceinline__ void ldsm2(unsigned* d, uint32_t a)
{
    asm volatile("ldmatrix.sync.aligned.m8n8.x2.shared.b16 {%0,%1}, [%2];"
        : "=r"(d[0]), "=r"(d[1]) : "r"(a));
}

__device__ __forceinline__ void ldsm2t(unsigned* d, uint32_t a)
{
    asm volatile("ldmatrix.sync.aligned.m8n8.x2.trans.shared.b16 {%0,%1}, [%2];"
        : "=r"(d[0]), "=r"(d[1]) : "r"(a));
}

__device__ __forceinline__ void cpasync16(uint32_t saddr, const void* gptr)
{
    asm volatile("cp.async.cg.shared.global [%0], [%1], 16;" :: "r"(saddr), "l"(gptr));
}
__device__ __forceinline__ void cpcommit() { asm volatile("cp.async.commit_group;"); }
template<int N> __device__ __forceinline__ void cpwaitN()
{ asm volatile("cp.async.wait_group %0;" :: "n"(N)); }

// ------------------------- weight transpose + split (merged launches) -------------------------
__device__ __forceinline__ void wtrans_tile(const float* Wz, bf16* ohz, bf16* olz,
                                            int K, int N, int n0, int k0)
{
    __shared__ float t[32][33];
    int tx = threadIdx.x & 31, ty = threadIdx.x >> 5;
    #pragma unroll
    for (int i = 0; i < 4; ++i)
        t[ty + 8*i][tx] = Wz[(size_t)(k0 + ty + 8*i) * N + n0 + tx];
    __syncthreads();
    #pragma unroll
    for (int i = 0; i < 4; ++i) {
        int n = n0 + ty + 8*i, k = k0 + tx;
        unsigned short h, l;
        fsplit(t[tx][ty + 8*i], h, l);
        ohz[(size_t)n * K + k] = __ushort_as_bfloat16(h);
        olz[(size_t)n * K + k] = __ushort_as_bfloat16(l);
    }
}

__global__ __launch_bounds__(256)
void wtransA_kernel(const float* __restrict__ qkvw, const float* __restrict__ w1)
{
    int z = blockIdx.z, bx = blockIdx.x, k0 = blockIdx.y * 32;
    if (bx < 48) {
        wtrans_tile(qkvw + (size_t)z*512*1536, g_qkvT_h + (size_t)z*1536*512,
                    g_qkvT_l + (size_t)z*1536*512, 512, 1536, bx*32, k0);
    } else {
        wtrans_tile(w1 + (size_t)z*512*2048, g_w1T_h + (size_t)z*2048*512,
                    g_w1T_l + (size_t)z*2048*512, 512, 2048, (bx-48)*32, k0);
    }
}

__global__ __launch_bounds__(256)
void wtransB_kernel(const float* __restrict__ rnetw, const float* __restrict__ ow,
                    const float* __restrict__ w2)
{
    int z = blockIdx.z, n0 = blockIdx.x * 32, by = blockIdx.y;
    if (by < 16) {
        wtrans_tile(rnetw + (size_t)z*512*512, g_rkT_h + (size_t)z*512*512,
                    g_rkT_l + (size_t)z*512*512, 512, 512, n0, by*32);
    } else if (by < 32) {
        wtrans_tile(ow + (size_t)z*512*512, g_oT_h + (size_t)z*512*512,
                    g_oT_l + (size_t)z*512*512, 512, 512, n0, (by-16)*32);
    } else {
        wtrans_tile(w2 + (size_t)z*2048*512, g_w2T_h + (size_t)z*512*2048,
                    g_w2T_l + (size_t)z*512*2048, 2048, 512, n0, (by-32)*32);
    }
}

// ------------------------- fused mask + positional embeddings + lengths ----------------------
__global__ void posmask_kernel(const unsigned char* __restrict__ raw,
                               unsigned char* __restrict__ pad,
                               bf16* __restrict__ ph, bf16* __restrict__ pl,
                               int* __restrict__ len)
{
    int gid = blockIdx.x * blockDim.x + threadIdx.x;
    unsigned char b0 = raw[0], b1 = raw[1];
    int mode = (b0 == 1 && b1 == 1) ? 0 : ((b0 == 1) ? 1 : 2);
    if (gid < B_ * T_) {
        bool m;
        if (mode == 0)      m = raw[gid] != 0;
        else if (mode == 1) m = ((const int*)raw)[gid] != 0;
        else                m = ((const float*)raw)[gid] != 0.0f;
        pad[gid] = m ? 0 : 1;
    }
    if (blockIdx.x == 0) {
        int w = threadIdx.x >> 5, lane = threadIdx.x & 31;
        for (int bb = w; bb < B_; bb += 8) {
            int s = 0;
            #pragma unroll
            for (int k = 0; k < 16; ++k) {
                int idx = bb * 512 + lane + 32 * k;
                bool m;
                if (mode == 0)      m = raw[idx] != 0;
                else if (mode == 1) m = ((const int*)raw)[idx] != 0;
                else                m = ((const float*)raw)[idx] != 0.0f;
                s += m ? 1 : 0;
            }
            #pragma unroll
            for (int o = 16; o; o >>= 1) s += __shfl_xor_sync(0xffffffffu, s, o);
            if (lane == 0) len[bb] = s;
        }
    }
    int idx = gid - B_ * T_;
    if (idx < 0 || idx >= 2048 * D_) return;
    int m2 = idx / D_;
    int k = idx - m2 * D_;
    int grp = m2 >> 10;
    int mm  = m2 & 1023;
    float p = (grp == 0) ? (float)(T_ - mm) : (float)(mm - T_);
    int kk = (k < 256) ? k : (k - 256);
    float invf = powf(10000.0f, -((float)(2 * kk) / (float)D_));
    float s = p * invf;
    float v = (k < 256) ? sinf(s) : cosf(s);
    unsigned short h, l;
    fsplit(v, h, l);
    ph[idx] = __ushort_as_bfloat16(h);
    pl[idx] = __ushort_as_bfloat16(l);
}

// ------------------------- layernorm v3: warp-per-row, no smem, no barrier -------------------
__global__ __launch_bounds__(256)
void ln3_kernel(const float* __restrict__ x, const float* __restrict__ addv,
                const float* __restrict__ g, const float* __restrict__ be,
                float* __restrict__ out_seq, bf16* __restrict__ outh, bf16* __restrict__ outl,
                float* __restrict__ outb0, float* __restrict__ outb1, int in_bt)
{
    int w = threadIdx.x >> 5, lane = threadIdx.x & 31;
    int row = blockIdx.x * 8 + w;
    int t = row / B_, b = row - t * B_;
    size_t iseq = (size_t)row * D_;
    size_t ibt  = ((size_t)b * T_ + t) * D_;
    const float* px = x + (in_bt ? ibt : iseq);
    float4 v[4];
    #pragma unroll
    for (int k = 0; k < 4; ++k) v[k] = ((const float4*)px)[lane + 32*k];
    if (addv) {
        #pragma unroll
        for (int k = 0; k < 4; ++k) {
            float4 a = ((const float4*)(addv + iseq))[lane + 32*k];
            v[k].x += a.x; v[k].y += a.y; v[k].z += a.z; v[k].w += a.w;
        }
    }
    float s = 0.f, q = 0.f;
    #pragma unroll
    for (int k = 0; k < 4; ++k) {
        s += v[k].x + v[k].y + v[k].z + v[k].w;
        q += v[k].x*v[k].x + v[k].y*v[k].y + v[k].z*v[k].z + v[k].w*v[k].w;
    }
    #pragma unroll
    for (int o = 16; o; o >>= 1) {
        s += __shfl_xor_sync(0xffffffffu, s, o);
        q += __shfl_xor_sync(0xffffffffu, q, o);
    }
    float mean = s * (1.0f / 512.0f);
    float var  = q * (1.0f / 512.0f) - mean * mean;
    float rs = rsqrtf(var + 1e-6f);
    #pragma unroll
    for (int k = 0; k < 4; ++k) {
        float4 gg = ((const float4*)g)[lane + 32*k];
        float4 bb = ((const float4*)be)[lane + 32*k];
        float4 y;
        y.x = (v[k].x - mean) * rs * gg.x + bb.x;
        y.y = (v[k].y - mean) * rs * gg.y + bb.y;
        y.z = (v[k].z - mean) * rs * gg.z + bb.z;
        y.w = (v[k].w - mean) * rs * gg.w + bb.w;
        ((float4*)(out_seq + iseq))[lane + 32*k] = y;
        unsigned short h0,l0,h1,l1,h2,l2,h3,l3;
        fsplit(y.x, h0, l0); fsplit(y.y, h1, l1);
        fsplit(y.z, h2, l2); fsplit(y.w, h3, l3);
        uint2 ph = { (unsigned)h0 | ((unsigned)h1<<16), (unsigned)h2 | ((unsigned)h3<<16) };
        uint2 pl = { (unsigned)l0 | ((unsigned)l1<<16), (unsigned)l2 | ((unsigned)l3<<16) };
        ((uint2*)(outh + iseq))[lane + 32*k] = ph;
        ((uint2*)(outl + iseq))[lane + 32*k] = pl;
        if (outb0) ((float4*)(outb0 + ibt))[lane + 32*k] = y;
        if (outb1) ((float4*)(outb1 + ibt))[lane + 32*k] = y;
    }
}

// ------------------------- GEMM v3 (dense layers), LDSM fragments -------------------------
// MODE 0: Cf fp32 (+bias);  MODE 1: bias+relu+split;  MODE 2: QKV epilogue;  MODE 4: split row-major
// blockIdx.z selects an independent problem: B += z*zStrB, O/Cf += z*zStrO.
template<int BM, int BN, int WM, int WN, int MODE>
__global__ void __launch_bounds__(256)
gemm_v3(const bf16* __restrict__ Ah, const bf16* __restrict__ Al,
        const bf16* __restrict__ Bh, const bf16* __restrict__ Bl,
        const float* __restrict__ bias, const float* __restrict__ bias2,
        float* __restrict__ Cf, bf16* __restrict__ Oh, bf16* __restrict__ Ol,
        int M, int N, int K, size_t zStrB, size_t zStrO)
{
    constexpr int MT = WM / 16, NT = WN / 8;
    constexpr int NWM = BM / WM;
    constexpr int NA = BM * 4, NB = BN * 4, TOTAL = 2 * (NA + NB);
    constexpr int SA = BM * 20, SB = BN * 20;
    constexpr int S = 2 * SA + 2 * SB;

    extern __shared__ uint32_t smem[];
    uint32_t sbase = (uint32_t)__cvta_generic_to_shared(smem);

    size_t zb_off = (size_t)blockIdx.z * zStrB;
    size_t zo_off = (size_t)blockIdx.z * zStrO;
    Bh += zb_off; Bl += zb_off;
    if (Oh) { Oh += zo_off; Ol += zo_off; }
    if (Cf) Cf += zo_off;

    int m0 = blockIdx.y * BM, n0 = blockIdx.x * BN;
    int tid = threadIdx.x, lane = tid & 31, w = tid >> 5;
    int wm = (w % NWM) * WM, wn = (w / NWM) * WN;
    int r = lane >> 2, c = lane & 3;

    float acc[MT][NT][4];
    #pragma unroll
    for (int i = 0; i < MT; ++i)
        #pragma unroll
        for (int j = 0; j < NT; ++j)
            #pragma unroll
            for (int q = 0; q < 4; ++q) acc[i][j][q] = 0.f;

    auto prefetch = [&](int kt, int st) {
        uint32_t base = sbase + (uint32_t)st * S * 4;
        #pragma unroll
        for (int l = 0; l < TOTAL / 256; ++l) {
            int q = tid + l * 256;
            const bf16* gp; uint32_t off;
            if (q < NA) {
                int row = q >> 2, seg = q & 3;
                gp = Ah + (size_t)(m0 + row) * K + kt + seg * 8;
                off = row * 20 + seg * 4;
            } else if (q < 2 * NA) {
                int p = q - NA; int row = p >> 2, seg = p & 3;
                gp = Al + (size_t)(m0 + row) * K + kt + seg * 8;
                off = SA + row * 20 + seg * 4;
            } else if (q < 2 * NA + NB) {
                int p = q - 2 * NA; int row = p >> 2, seg = p & 3;
                gp = Bh + (size_t)(n0 + row) * K + kt + seg * 8;
                off = 2 * SA + row * 20 + seg * 4;
            } else {
                int p = q - 2 * NA - NB; int row = p >> 2, seg = p & 3;
                gp = Bl + (size_t)(n0 + row) * K + kt + seg * 8;
                off = 2 * SA + SB + row * 20 + seg * 4;
            }
            cpasync16(base + off * 4, gp);
        }
        cpcommit();
    };

    uint32_t aRowOff = (lane & 7) + ((lane >> 3) & 1) * 8;
    uint32_t aChunk  = (lane >> 4) * 16;
    uint32_t bRowOff = lane & 7;
    uint32_t bChunk  = ((lane >> 3) & 1) * 16;

    auto compute = [&](int st) {
        uint32_t stb = sbase + (uint32_t)st * S * 4;
        #pragma unroll
        for (int ks = 0; ks < 2; ++ks) {
            unsigned ah[MT][4], al[MT][4];
            #pragma unroll
            for (int mt = 0; mt < MT; ++mt) {
                uint32_t ab = stb + (uint32_t)(wm + mt * 16 + aRowOff) * 80 + ks * 32 + aChunk;
                ldsm4(ah[mt], ab);
                ldsm4(al[mt], ab + SA * 4);
            }
            #pragma unroll
            for (int nt = 0; nt < NT; ++nt) {
                uint32_t bb = stb + 2u * SA * 4 + (uint32_t)(wn + nt * 8 + bRowOff) * 80
                              + ks * 32 + bChunk;
                unsigned bh[2], bl[2];
                ldsm2(bh, bb);
                ldsm2(bl, bb + SB * 4);
                #pragma unroll
                for (int mt = 0; mt < MT; ++mt) {
                    mma16816(acc[mt][nt], ah[mt], bh);
                    mma16816(acc[mt][nt], ah[mt], bl);
                    mma16816(acc[mt][nt], al[mt], bh);
                }
            }
        }
    };

    int nk = K / 32;
    prefetch(0, 0);
    for (int i = 0; i < nk; ++i) {
        cpwaitN<0>();
        __syncthreads();
        if (i + 1 < nk) prefetch((i + 1) * 32, (i + 1) & 1);
        compute(i & 1);
    }

    #pragma unroll
    for (int mt = 0; mt < MT; ++mt) {
        int row = m0 + wm + mt * 16 + r;
        #pragma unroll
        for (int nt = 0; nt < NT; ++nt) {
            int col = n0 + wn + nt * 8 + 2 * c;
            float v0 = acc[mt][nt][0], v1 = acc[mt][nt][1];
            float v2 = acc[mt][nt][2], v3 = acc[mt][nt][3];
            if (MODE == 0) {
                if (bias) { v0 += bias[col]; v1 += bias[col+1]; v2 += bias[col]; v3 += bias[col+1]; }
                float2 w0 = {v0, v1}, w1 = {v2, v3};
                *(float2*)(Cf + (size_t)row * N + col) = w0;
                *(float2*)(Cf + (size_t)(row + 8) * N + col) = w1;
            } else if (MODE == 1) {
                float bb0 = bias[col], bb1 = bias[col+1];
                v0 = fmaxf(v0 + bb0, 0.f); v1 = fmaxf(v1 + bb1, 0.f);
                v2 = fmaxf(v2 + bb0, 0.f); v3 = fmaxf(v3 + bb1, 0.f);
                split2_store(Oh, Ol, (size_t)row * N + col, v0, v1);
                split2_store(Oh, Ol, (size_t)(row + 8) * N + col, v2, v3);
            } else if (MODE == 2) {
                if (col < 512) {
                    int hn = col >> 6, d = col & 63;
                    float rw0 = bias[col], rw1 = bias[col+1];
                    float rr0 = bias2[col], rr1 = bias2[col+1];
                    {
                        int bb = row & 15, tt = row >> 4;
                        size_t base = ((size_t)(bb*8+hn)*512 + tt)*64 + d;
                        split2_store(g_qw_h, g_qw_l, base, (v0+rw0)*SCALE_, (v1+rw1)*SCALE_);
                        split2_store(g_qr_h, g_qr_l, base, (v0+rr0)*SCALE_, (v1+rr1)*SCALE_);
                    }
                    {
                        int r2 = row + 8;
                        int bb = r2 & 15, tt = r2 >> 4;
                        size_t base = ((size_t)(bb*8+hn)*512 + tt)*64 + d;
                        split2_store(g_qw_h, g_qw_l, base, (v2+rw0)*SCALE_, (v3+rw1)*SCALE_);
                        split2_store(g_qr_h, g_qr_l, base, (v2+rr0)*SCALE_, (v3+rr1)*SCALE_);
                    }
                } else if (col < 1024) {
                    int cc = col - 512;
                    int hn = cc >> 6, d = cc & 63;
                    {
                        int bb = row & 15, tt = row >> 4;
                        size_t base = ((size_t)(bb*8+hn)*512 + tt)*64 + d;
                        split2_store(g_k_h, g_k_l, base, v0, v1);
                    }
                    {
                        int r2 = row + 8;
                        int bb = r2 & 15, tt = r2 >> 4;
                        size_t base = ((size_t)(bb*8+hn)*512 + tt)*64 + d;
                        split2_store(g_k_h, g_k_l, base, v2, v3);
                    }
                } else {
                    // V row-major [(z)*512+t][d] — coalesced, same pattern as K
                    int dp = col - 1024;
                    int hn = dp >> 6, d = dp & 63;
                    {
                        int bb = row & 15, tt = row >> 4;
                        size_t base = ((size_t)(bb*8+hn)*512 + tt)*64 + d;
                        split2_store(g_vth, g_vtl, base, v0, v1);
                    }
                    {
                        int r2 = row + 8;
                        int bb = r2 & 15, tt = r2 >> 4;
                        size_t base = ((size_t)(bb*8+hn)*512 + tt)*64 + d;
                        split2_store(g_vth, g_vtl, base, v2, v3);
                    }
                }
            } else { // MODE 4
                split2_store(Oh, Ol, (size_t)row * N + col, v0, v1);
                split2_store(Oh, Ol, (size_t)(row + 8) * N + col, v2, v3);
            }
        }
    }
}

// ------------------------- fused attention (64-row, 3-deep, unrolled + predicated skip) ------
#define ARENA_ROW 532
#define ARENA_U32 (64*ARENA_ROW)
#define STRM_OFF  ARENA_U32
#define TILE_U32  5120
#define VT_TILE_U32 2304                 // 2 comps x 32 rows x 36 u32 (pitch 144B)
#define QBUF_OFF  (STRM_OFF + 3*TILE_U32)
#define ATTN_SMEM_U32 (QBUF_OFF + TILE_U32)
#define ATTN_SMEM_BYTES (ATTN_SMEM_U32*4)        // 218112
#define P_LO_OFF 272

__device__ __forceinline__ void load_tile64x64(uint32_t sb, const bf16* gh, const bf16* gl,
                                               int r0, int ld)
{
    int tid = threadIdx.x;
    #pragma unroll
    for (int l = 0; l < 4; ++l) {
        int q = tid + l*256;
        int comp = q >> 9, p = q & 511;
        int row = p >> 3, seg = p & 7;
        int kc = seg >> 2, u = (seg & 3) * 4;
        const bf16* g = (comp ? gl : gh) + (size_t)(r0 + row) * ld + seg * 8;
        uint32_t off = (uint32_t)(comp * 2560 + kc * 1280 + row * 20 + u);
        cpasync16(sb + off * 4, g);
    }
}

// V tile: 32 t-rows x 64 d (row-major [t][d], ld=64), pitch 36 u32 per row
__device__ __forceinline__ void load_vtile(uint32_t sb, const bf16* gh, const bf16* gl, int t0)
{
    int tid = threadIdx.x;
    #pragma unroll
    for (int l = 0; l < 2; ++l) {
        int q = tid + l*256;
        int comp = q >> 8, p = q & 255;
        int row = p >> 3, seg = p & 7;
        const bf16* g = (comp ? gl : gh) + (size_t)(t0 + row) * 64 + seg * 8;
        uint32_t off = (uint32_t)(comp * 1152 + row * 36 + seg * 4);
        cpasync16(sb + off * 4, g);
    }
}

__device__ __forceinline__ void mma_qt(float acc[2][2][4], uint32_t sbase,
                                       int qoff, int toff, int wm, int wn, int lane)
{
    uint32_t aRowOff = (lane & 7) + ((lane >> 3) & 1) * 8;
    uint32_t aChunk  = (lane >> 4) * 16;
    uint32_t bRowOff = lane & 7;
    uint32_t bChunk  = ((lane >> 3) & 1) * 16;
    #pragma unroll
    for (int kc = 0; kc < 2; ++kc) {
        uint32_t qb = sbase + (uint32_t)(qoff + kc*1280) * 4;
        uint32_t tb = sbase + (uint32_t)(toff + kc*1280) * 4;
        #pragma unroll
        for (int ks = 0; ks < 2; ++ks) {
            unsigned ah[2][4], al[2][4];
            #pragma unroll
            for (int mt = 0; mt < 2; ++mt) {
                uint32_t ab = qb + (uint32_t)(wm + mt*16 + aRowOff) * 80 + ks*32 + aChunk;
                ldsm4(ah[mt], ab);
                ldsm4(al[mt], ab + 2560*4);
            }
            #pragma unroll
            for (int nt = 0; nt < 2; ++nt) {
                uint32_t bb = tb + (uint32_t)(wn + nt*8 + bRowOff) * 80 + ks*32 + bChunk;
                unsigned bh[2], bl[2];
                ldsm2(bh, bb);
                ldsm2(bl, bb + 2560*4);
                #pragma unroll
                for (int mt = 0; mt < 2; ++mt) {
                    mma16816(acc[mt][nt], ah[mt], bh);
                    mma16816(acc[mt][nt], ah[mt], bl);
                    mma16816(acc[mt][nt], al[mt], bh);
                }
            }
        }
    }
}

__global__ __launch_bounds__(256)
void attn_fused(const bf16* __restrict__ qwh, const bf16* __restrict__ qwl,
                const bf16* __restrict__ qrh, const bf16* __restrict__ qrl,
                const bf16* __restrict__ kh,  const bf16* __restrict__ kl,
                const bf16* __restrict__ rkh, const bf16* __restrict__ rkl,
                const bf16* __restrict__ vth, const bf16* __restrict__ vtl,
                const unsigned char* __restrict__ pad,
                bf16* __restrict__ vech, bf16* __restrict__ vecl)
{
    extern __shared__ uint32_t sm[];
    float* Sf = (float*)sm;
    uint32_t sb = (uint32_t)__cvta_generic_to_shared(sm);

    int i0 = blockIdx.x * 64;
    int z = blockIdx.y;
    int zb = z >> 3, zn = z & 7;
    int grp = (zb >= 8) ? 1 : 0;
    int tid = threadIdx.x, lane = tid & 31, w = tid >> 5;
    int wm = (w & 1) * 32, wn = (w >> 1) * 16;
    int r = lane >> 2, c = lane & 3;

    int len = g_len[zb];
    int ajt = (len + 63) >> 6;                     // active Phase A j-tiles
    int bmt = min(9, ((len + 62) >> 6) + 1);       // active Phase B m-tiles
    int dkt = (len + 31) >> 5;                     // active Phase D k-tiles

    const size_t zoff = (size_t)z * 512 * 64;
    const bf16* pqwh = qwh + zoff; const bf16* pqwl = qwl + zoff;
    const bf16* pqrh = qrh + zoff; const bf16* pqrl = qrl + zoff;
    const bf16* pkh  = kh  + zoff; const bf16* pkl  = kl  + zoff;
    const bf16* pvth = vth + zoff; const bf16* pvtl = vtl + zoff;
    int m_lo = 449 - i0;
    const bf16* prkh = rkh + ((size_t)(grp*1024 + m_lo)) * 512 + zn * 64;
    const bf16* prkl = rkl + ((size_t)(grp*1024 + m_lo)) * 512 + zn * 64;

    // ---- Phase A: S = qw @ k^T (constant-trip, predicated work) ----
    load_tile64x64(sb + QBUF_OFF*4, pqwh, pqwl, i0, 64);
    load_tile64x64(sb + STRM_OFF*4, pkh, pkl, 0, 64);
    cpcommit();
    if (1 < ajt) load_tile64x64(sb + (STRM_OFF + TILE_U32)*4, pkh, pkl, 64, 64);
    cpcommit();
    #pragma unroll
    for (int jt = 0; jt < 8; ++jt) {
        if (jt + 2 < ajt)
            load_tile64x64(sb + (STRM_OFF + ((jt+2)%3)*TILE_U32)*4, pkh, pkl, (jt+2)*64, 64);
        cpcommit();
        cpwaitN<2>();
        __syncthreads();
        if (jt < ajt) {
            float acc[2][2][4] = {};
            mma_qt(acc, sb, QBUF_OFF, STRM_OFF + (jt%3)*TILE_U32, wm, wn, lane);
            #pragma unroll
            for (int mt = 0; mt < 2; ++mt) {
                int il = wm + mt*16 + r;
                #pragma unroll
                for (int nt = 0; nt < 2; ++nt) {
                    int j = jt*64 + wn + nt*8 + 2*c;
                    *(float2*)(Sf + il*ARENA_ROW + j)     = make_float2(acc[mt][nt][0], acc[mt][nt][1]);
                    *(float2*)(Sf + (il+8)*ARENA_ROW + j) = make_float2(acc[mt][nt][2], acc[mt][nt][3]);
                }
            }
        }
        __syncthreads();
    }
    cpwaitN<0>();

    // ---- Phase B: E = qr @ rk_band^T, scatter-add (constant-trip, predicated) ----
    load_tile64x64(sb + QBUF_OFF*4, pqrh, pqrl, i0, 64);
    load_tile64x64(sb + STRM_OFF*4, prkh, prkl, 0, 512);
    cpcommit();
    if (1 < bmt) load_tile64x64(sb + (STRM_OFF + TILE_U32)*4, prkh, prkl, 64, 512);
    cpcommit();
    #pragma unroll
    for (int mt9 = 0; mt9 < 9; ++mt9) {
        if (mt9 + 2 < bmt)
            load_tile64x64(sb + (STRM_OFF + ((mt9+2)%3)*TILE_U32)*4, prkh, prkl, (mt9+2)*64, 512);
        cpcommit();
        cpwaitN<2>();
        __syncthreads();
        if (mt9 < bmt) {
            float acc[2][2][4] = {};
            mma_qt(acc, sb, QBUF_OFF, STRM_OFF + (mt9%3)*TILE_U32, wm, wn, lane);
            #pragma unroll
            for (int mt = 0; mt < 2; ++mt) {
                #pragma unroll
                for (int nt = 0; nt < 2; ++nt) {
                    int mloc = mt9*64 + wn + nt*8 + 2*c;
                    int il = wm + mt*16 + r;
                    int j = mloc + il - 63;
                    if (j >= 0   && j < 512)   Sf[il*ARENA_ROW + j]       += acc[mt][nt][0];
                    if (j+1 >= 0 && j+1 < 512) Sf[il*ARENA_ROW + j + 1]   += acc[mt][nt][1];
                    int il2 = il + 8;
                    int j2 = mloc + il2 - 63;
                    if (j2 >= 0   && j2 < 512)   Sf[il2*ARENA_ROW + j2]     += acc[mt][nt][2];
                    if (j2+1 >= 0 && j2+1 < 512) Sf[il2*ARENA_ROW + j2 + 1] += acc[mt][nt][3];
                }
            }
        }
        __syncthreads();
    }
    cpwaitN<0>();

    // ---- Phase C: mask + softmax + in-place split-P ----
    {
        const unsigned char* pb = pad + zb * T_;
        for (int rr = 0; rr < 8; ++rr) {
            int il = w*8 + rr;
            float* row = Sf + il*ARENA_ROW;
            float vv[16];
            #pragma unroll
            for (int q4 = 0; q4 < 4; ++q4) {
                int jb = (lane + 32*q4) * 4;
                float4 t = *(float4*)(row + jb);
                unsigned pm = *(const unsigned*)(pb + jb);
                vv[q4*4+0] = (pm & 0xffu)        ? NEG_INF_ : t.x;
                vv[q4*4+1] = (pm & 0xff00u)      ? NEG_INF_ : t.y;
                vv[q4*4+2] = (pm & 0xff0000u)    ? NEG_INF_ : t.z;
                vv[q4*4+3] = (pm & 0xff000000u)  ? NEG_INF_ : t.w;
            }
            float mx = vv[0];
            #pragma unroll
            for (int i = 1; i < 16; ++i) mx = fmaxf(mx, vv[i]);
            #pragma unroll
            for (int o = 16; o; o >>= 1) mx = fmaxf(mx, __shfl_xor_sync(0xffffffffu, mx, o));
            float s = 0.f;
            #pragma unroll
            for (int i = 0; i < 16; ++i) { vv[i] = __expf(vv[i] - mx); s += vv[i]; }
            #pragma unroll
            for (int o = 16; o; o >>= 1) s += __shfl_xor_sync(0xffffffffu, s, o);
            float inv = 1.0f / s;
            uint32_t* rh = sm + il*ARENA_ROW;
            uint32_t* rl = rh + P_LO_OFF;
            #pragma unroll
            for (int q4 = 0; q4 < 4; ++q4) {
                int jj = (lane + 32*q4) * 2;
                unsigned short h0,l0,h1,l1,h2,l2,h3,l3;
                fsplit(vv[q4*4+0]*inv, h0, l0);
                fsplit(vv[q4*4+1]*inv, h1, l1);
                fsplit(vv[q4*4+2]*inv, h2, l2);
                fsplit(vv[q4*4+3]*inv, h3, l3);
                uint2 ph = { (unsigned)h0 | ((unsigned)h1<<16), (unsigned)h2 | ((unsigned)h3<<16) };
                uint2 pl = { (unsigned)l0 | ((unsigned)l1<<16), (unsigned)l2 | ((unsigned)l3<<16) };
                *(uint2*)(rh + jj) = ph;
                *(uint2*)(rl + jj) = pl;
            }
        }
    }
    __syncthreads();

    // ---- Phase D: vec = P @ V (trans-LDSM B fragments from row-major V) ----
    uint32_t aRowOff = (lane & 7) + ((lane >> 3) & 1) * 8;
    uint32_t aChunk  = (lane >> 4) * 16;
    uint32_t tRow    = lane & 15;
    load_vtile(sb + STRM_OFF*4, pvth, pvtl, 0);
    cpcommit();
    if (1 < dkt) load_vtile(sb + (STRM_OFF + VT_TILE_U32)*4, pvth, pvtl, 32);
    cpcommit();
    float acc[2][2][4] = {};
    #pragma unroll
    for (int kt = 0; kt < 16; ++kt) {
        if (kt + 2 < dkt)
            load_vtile(sb + (STRM_OFF + ((kt+2)%3)*VT_TILE_U32)*4, pvth, pvtl, (kt+2)*32);
        cpcommit();
        cpwaitN<2>();
        __syncthreads();
        if (kt < dkt) {
            uint32_t tbb = sb + (uint32_t)(STRM_OFF + (kt%3)*VT_TILE_U32) * 4;
            #pragma unroll
            for (int ks = 0; ks < 2; ++ks) {
                int g16 = kt*2 + ks;
                unsigned ah[2][4], al[2][4];
                #pragma unroll
                for (int mt = 0; mt < 2; ++mt) {
                    uint32_t ab = sb + (uint32_t)(wm + mt*16 + aRowOff) * (ARENA_ROW*4)
                                  + (uint32_t)g16 * 32 + aChunk;
                    ldsm4(ah[mt], ab);
                    ldsm4(al[mt], ab + P_LO_OFF*4);
                }
                #pragma unroll
                for (int nt = 0; nt < 2; ++nt) {
                    uint32_t bb = tbb + (uint32_t)(ks*16 + tRow) * 144 + (uint32_t)(wn + nt*8) * 2;
                    unsigned bh[2], bl[2];
                    ldsm2t(bh, bb);
                    ldsm2t(bl, bb + 1152*4);
                    #pragma unroll
                    for (int mt = 0; mt < 2; ++mt) {
                        mma16816(acc[mt][nt], ah[mt], bh);
                        mma16816(acc[mt][nt], ah[mt], bl);
                        mma16816(acc[mt][nt], al[mt], bh);
                    }
                }
            }
        }
        __syncthreads();
    }
    cpwaitN<0>();
    #pragma unroll
    for (int mt = 0; mt < 2; ++mt) {
        int i = i0 + wm + mt*16 + r;
        #pragma unroll
        for (int nt = 0; nt < 2; ++nt) {
            int d = wn + nt*8 + 2*c;
            size_t o0 = ((size_t)i * B_ + zb) * 512 + zn * 64 + d;
            size_t o1 = ((size_t)(i + 8) * B_ + zb) * 512 + zn * 64 + d;
            split2_store(vech, vecl, o0, acc[mt][nt][0], acc[mt][nt][1]);
            split2_store(vech, vecl, o1, acc[mt][nt][2], acc[mt][nt][3]);
        }
    }
}

// ------------------------- host orchestration -------------------------
template <typename Tp>
static Tp* symaddr(const void* sym)
{
    void* p = nullptr;
    cudaGetSymbolAddress(&p, sym);
    return (Tp*)p;
}

extern "C" void kernel_launch(void* const* d_in, const int* in_sizes, int n_in,
                              void* d_out, int out_size)
{
    const float* h_in  = (const float*)d_in[0];
    const void*  mraw  = d_in[1];
    const float* rwb   = (const float*)d_in[2];
    const float* rrb   = (const float*)d_in[3];
    const float* tlg   = (const float*)d_in[4];
    const float* tlb   = (const float*)d_in[5];
    const float* qkvw  = (const float*)d_in[6];
    const float* rnetw = (const float*)d_in[7];
    const float* ow    = (const float*)d_in[8];
    const float* alg   = (const float*)d_in[9];
    const float* alb   = (const float*)d_in[10];
    const float* w1    = (const float*)d_in[11];
    const float* b1    = (const float*)d_in[12];
    const float* w2    = (const float*)d_in[13];
    const float* b2    = (const float*)d_in[14];
    const float* flg   = (const float*)d_in[15];
    const float* flb   = (const float*)d_in[16];
    float* out = (float*)d_out;

    float* p_h    = symaddr<float>(g_h);
    bf16*  p_hh   = symaddr<bf16>(g_hh);
    bf16*  p_hl   = symaddr<bf16>(g_hl);
    bf16*  p_posh = symaddr<bf16>(g_posh);
    bf16*  p_posl = symaddr<bf16>(g_posl);
    bf16*  p_qw_h = symaddr<bf16>(g_qw_h); bf16* p_qw_l = symaddr<bf16>(g_qw_l);
    bf16*  p_qr_h = symaddr<bf16>(g_qr_h); bf16* p_qr_l = symaddr<bf16>(g_qr_l);
    bf16*  p_k_h  = symaddr<bf16>(g_k_h);  bf16* p_k_l  = symaddr<bf16>(g_k_l);
    bf16*  p_vth  = symaddr<bf16>(g_vth);  bf16* p_vtl  = symaddr<bf16>(g_vtl);
    bf16*  p_rkbf_h = symaddr<bf16>(g_rkbf_h); bf16* p_rkbf_l = symaddr<bf16>(g_rkbf_l);
    bf16*  p_vech = symaddr<bf16>(g_vech);
    bf16*  p_vecl = symaddr<bf16>(g_vecl);
    float* p_t1   = symaddr<float>(g_t1);
    bf16*  p_ffh  = symaddr<bf16>(g_ffh);
    bf16*  p_ffl  = symaddr<bf16>(g_ffl);
    unsigned char* p_pad = symaddr<unsigned char>(g_pad);
    int*   p_len  = symaddr<int>(g_len);

    bf16* p_qkvT_h = symaddr<bf16>(g_qkvT_h); bf16* p_qkvT_l = symaddr<bf16>(g_qkvT_l);
    bf16* p_rkT_h  = symaddr<bf16>(g_rkT_h);  bf16* p_rkT_l  = symaddr<bf16>(g_rkT_l);
    bf16* p_oT_h   = symaddr<bf16>(g_oT_h);   bf16* p_oT_l   = symaddr<bf16>(g_oT_l);
    bf16* p_w1T_h  = symaddr<bf16>(g_w1T_h);  bf16* p_w1T_l  = symaddr<bf16>(g_w1T_l);
    bf16* p_w2T_h  = symaddr<bf16>(g_w2T_h);  bf16* p_w2T_l  = symaddr<bf16>(g_w2T_l);

    auto k_qkv = gemm_v3<128,128,64,32,2>;
    auto k_rk  = gemm_v3<128,128,64,32,4>;
    auto k_f32 = gemm_v3<128,128,64,32,0>;
    auto k_ff1 = gemm_v3<128,128,64,32,1>;
    const int SMEM_BIG = (2*128*20 + 2*128*20) * 4 * 2;
    cudaFuncSetAttribute(k_qkv, cudaFuncAttributeMaxDynamicSharedMemorySize, SMEM_BIG);
    cudaFuncSetAttribute(k_rk,  cudaFuncAttributeMaxDynamicSharedMemorySize, SMEM_BIG);
    cudaFuncSetAttribute(k_f32, cudaFuncAttributeMaxDynamicSharedMemorySize, SMEM_BIG);
    cudaFuncSetAttribute(k_ff1, cudaFuncAttributeMaxDynamicSharedMemorySize, SMEM_BIG);
    cudaFuncSetAttribute(attn_fused, cudaFuncAttributeMaxDynamicSharedMemorySize, ATTN_SMEM_BYTES);

    const size_t BTD = (size_t)B_ * T_ * D_;
    const size_t RKL = (size_t)RKROWS * 512;

    // pre-loop
    wtransA_kernel<<<dim3(112, 16, L_), 256>>>(qkvw, w1);
    wtransB_kernel<<<dim3(16, 96, L_), 256>>>(rnetw, ow, w2);
    posmask_kernel<<<(2048*D_ + B_*T_ + 255)/256, 256>>>(
        (const unsigned char*)mraw, p_pad, p_posh, p_posl, p_len);
    ln3_kernel<<<T_*B_/8, 256>>>(h_in, nullptr, tlg, tlb, p_h, p_hh, p_hl, out + BTD, nullptr, 1);
    // ALL layers' rk GEMMs in one launch (z = layer)
    k_rk<<<dim3(512/128, 2048/128, L_), 256, SMEM_BIG>>>(
        p_posh, p_posl, p_rkT_h, p_rkT_l,
        nullptr, nullptr, nullptr, p_rkbf_h, p_rkbf_l, 2048, 512, 512,
        (size_t)512*512, RKL);

    for (int i = 0; i < L_; ++i) {
        // QKV -> qw/qr/k/v (split, per-head layouts; V row-major like K)
        k_qkv<<<dim3(1536/128, (T_*B_)/128), 256, SMEM_BIG>>>(
            p_hh, p_hl, p_qkvT_h + (size_t)i*1536*512, p_qkvT_l + (size_t)i*1536*512,
            rwb, rrb, nullptr, nullptr, nullptr, T_*B_, 1536, 512, 0, 0);
        // fused attention (length-aware, unrolled), layer-i rk slice
        attn_fused<<<dim3(T_/64, B_*H_), 256, ATTN_SMEM_BYTES>>>(
            p_qw_h, p_qw_l, p_qr_h, p_qr_l, p_k_h, p_k_l,
            p_rkbf_h + (size_t)i*RKL, p_rkbf_l + (size_t)i*RKL,
            p_vth, p_vtl, p_pad, p_vech, p_vecl);
        // O proj
        k_f32<<<dim3(512/128, (T_*B_)/128), 256, SMEM_BIG>>>(
            p_vech, p_vecl, p_oT_h + (size_t)i*512*512, p_oT_l + (size_t)i*512*512,
            nullptr, nullptr, p_t1, nullptr, nullptr, T_*B_, 512, 512, 0, 0);
        // out1 = LN(h + attn)
        ln3_kernel<<<T_*B_/8, 256>>>(p_h, p_t1, alg + i*D_, alb + i*D_, p_h, p_hh, p_hl,
                                     nullptr, nullptr, 0);
        // FF1
        k_ff1<<<dim3(DI_/128, (T_*B_)/128), 256, SMEM_BIG>>>(
            p_hh, p_hl, p_w1T_h + (size_t)i*2048*512, p_w1T_l + (size_t)i*2048*512,
            b1 + (size_t)i*DI_, nullptr, nullptr, p_ffh, p_ffl, T_*B_, DI_, 512, 0, 0);
        // FF2
        k_f32<<<dim3(512/128, (T_*B_)/128), 256, SMEM_BIG>>>(
            p_ffh, p_ffl, p_w2T_h + (size_t)i*512*2048, p_w2T_l + (size_t)i*512*2048,
            b2 + (size_t)i*D_, nullptr, p_t1, nullptr, nullptr, T_*B_, 512, DI_, 0, 0);
        // layer out = LN(out1 + ff)
        float* hb0 = out + (size_t)(2 + i) * BTD;
        float* hb1 = (i == L_ - 1) ? out : nullptr;
        ln3_kernel<<<T_*B_/8, 256>>>(p_h, p_t1, flg + i*D_, flb + i*D_, p_h, p_hh, p_hl,
                                     hb0, hb1, 0);
    }
}